// round 2
// baseline (speedup 1.0000x reference)
#include <cuda_runtime.h>
#include <math.h>

// Problem constants
#define NN_ 16384
#define MM_ 8192
#define DD_ 512
#define FF_ 2048

// ---------------- static scratch (no runtime allocation allowed) ----------------
__device__ float g_anorm[MM_];
__device__ float g_S[(size_t)NN_ * MM_];          // 512 MB: src @ anchor^T
__device__ float g_neigh[(size_t)NN_ * DD_];
__device__ float g_cat[(size_t)NN_ * 2 * DD_];    // [src | a_map]
__device__ float g_comb[(size_t)NN_ * DD_];
__device__ float g_combn[(size_t)NN_ * DD_];
__device__ float g_h[(size_t)NN_ * FF_];          // 128 MB
__device__ float g_r[(size_t)NN_ * DD_];
__device__ float g_comb2[(size_t)NN_ * DD_];
__device__ float g_dec[(size_t)NN_ * DD_];
__device__ float g_part[2 * 128 * DD_];           // BN partial sums
__device__ float g_scale[DD_];
__device__ float g_shift[DD_];

// ---------------- anchor squared norms ----------------
__global__ void anorm_kernel(const float* __restrict__ A) {
    int warp = threadIdx.x >> 5, lane = threadIdx.x & 31;
    int row = blockIdx.x * 8 + warp;
    const float* p = A + (size_t)row * DD_;
    float s = 0.f;
    for (int c = lane; c < DD_; c += 32) { float v = p[c]; s += v * v; }
    #pragma unroll
    for (int o = 16; o; o >>= 1) s += __shfl_xor_sync(0xffffffffu, s, o);
    if (lane == 0) g_anorm[row] = s;
}

// ---------------- generic tiled SGEMM ----------------
// C[row, col] = sum_k A[row,k] * (BT ? B[col,k] : B[k,col])  (+ epilogue)
// EPI: 0 = none, 1 = +bias, 2 = tanh(+bias), 3 = +bias +res
template <bool BT, int EPI>
__global__ __launch_bounds__(256) void gemm_kernel(
    const float* __restrict__ A, const float* __restrict__ B,
    const float* __restrict__ bias, const float* __restrict__ res,
    float* __restrict__ C, int K, int lda, int ldb, int ldc)
{
    __shared__ float As[16][128];
    __shared__ float Bs[16][128];
    const int tid = threadIdx.x;
    const int tcol = tid & 15, trow = tid >> 4;
    const int rowBase = blockIdx.y * 128;
    const int colBase = blockIdx.x * 128;

    float acc[8][8];
    #pragma unroll
    for (int i = 0; i < 8; i++)
        #pragma unroll
        for (int j = 0; j < 8; j++) acc[i][j] = 0.f;

    for (int k0 = 0; k0 < K; k0 += 16) {
        #pragma unroll
        for (int t = 0; t < 2; t++) {
            int v = tid + t * 256;
            int r = v >> 2, c4 = (v & 3) << 2;
            float4 a4 = *reinterpret_cast<const float4*>(
                A + (size_t)(rowBase + r) * lda + (k0 + c4));
            As[c4 + 0][r] = a4.x; As[c4 + 1][r] = a4.y;
            As[c4 + 2][r] = a4.z; As[c4 + 3][r] = a4.w;
            if (BT) {
                float4 b4 = *reinterpret_cast<const float4*>(
                    B + (size_t)(colBase + r) * ldb + (k0 + c4));
                Bs[c4 + 0][r] = b4.x; Bs[c4 + 1][r] = b4.y;
                Bs[c4 + 2][r] = b4.z; Bs[c4 + 3][r] = b4.w;
            } else {
                int br = v >> 5, bc = (v & 31) << 2;
                float4 b4 = *reinterpret_cast<const float4*>(
                    B + (size_t)(k0 + br) * ldb + (colBase + bc));
                *reinterpret_cast<float4*>(&Bs[br][bc]) = b4;
            }
        }
        __syncthreads();
        #pragma unroll
        for (int k = 0; k < 16; k++) {
            float ra[8], rb[8];
            #pragma unroll
            for (int i = 0; i < 8; i++) ra[i] = As[k][trow * 8 + i];
            #pragma unroll
            for (int j = 0; j < 8; j++) rb[j] = Bs[k][tcol * 8 + j];
            #pragma unroll
            for (int i = 0; i < 8; i++)
                #pragma unroll
                for (int j = 0; j < 8; j++) acc[i][j] += ra[i] * rb[j];
        }
        __syncthreads();
    }

    #pragma unroll
    for (int i = 0; i < 8; i++) {
        int row = rowBase + trow * 8 + i;
        #pragma unroll
        for (int j = 0; j < 8; j += 4) {
            int col = colBase + tcol * 8 + j;
            float4 v;
            v.x = acc[i][j + 0]; v.y = acc[i][j + 1];
            v.z = acc[i][j + 2]; v.w = acc[i][j + 3];
            if (EPI >= 1) {
                v.x += bias[col + 0]; v.y += bias[col + 1];
                v.z += bias[col + 2]; v.w += bias[col + 3];
            }
            if (EPI == 2) {
                v.x = tanhf(v.x); v.y = tanhf(v.y);
                v.z = tanhf(v.z); v.w = tanhf(v.w);
            }
            if (EPI == 3) {
                float4 rr = *reinterpret_cast<const float4*>(
                    res + (size_t)row * ldc + col);
                v.x += rr.x; v.y += rr.y; v.z += rr.z; v.w += rr.w;
            }
            *reinterpret_cast<float4*>(C + (size_t)row * ldc + col) = v;
        }
    }
}

// ---------------- top-5 + gather/mean ----------------
// d2 ranking uses anorm[m] - 2*dot (the per-row ||src||^2 term is rank-invariant).
// Lexicographic (value, index) compare matches top_k tie semantics (lower index wins).
__global__ __launch_bounds__(256) void topk_kernel(const float* __restrict__ anchors) {
    int n = blockIdx.x;
    const float* Srow = g_S + (size_t)n * MM_;
    float v[5]; int id[5];
    #pragma unroll
    for (int i = 0; i < 5; i++) { v[i] = 3.4e38f; id[i] = 0x7fffffff; }
    for (int m = threadIdx.x; m < MM_; m += 256) {
        float d = g_anorm[m] - 2.0f * Srow[m];
        if (d < v[4] || (d == v[4] && m < id[4])) {
            int p = 4;
            while (p > 0 && (d < v[p-1] || (d == v[p-1] && m < id[p-1]))) {
                v[p] = v[p-1]; id[p] = id[p-1]; p--;
            }
            v[p] = d; id[p] = m;
        }
    }
    __shared__ float sv[256];
    __shared__ int   si[256];
    __shared__ int   winners[5];
    int pos = 0;
    for (int round = 0; round < 5; round++) {
        sv[threadIdx.x] = (pos < 5) ? v[pos] : 3.4e38f;
        si[threadIdx.x] = (pos < 5) ? id[pos] : 0x7fffffff;
        __syncthreads();
        for (int s = 128; s > 0; s >>= 1) {
            if (threadIdx.x < s) {
                float ov = sv[threadIdx.x + s]; int oi = si[threadIdx.x + s];
                if (ov < sv[threadIdx.x] ||
                    (ov == sv[threadIdx.x] && oi < si[threadIdx.x])) {
                    sv[threadIdx.x] = ov; si[threadIdx.x] = oi;
                }
            }
            __syncthreads();
        }
        int w = si[0];
        if (threadIdx.x == 0) winners[round] = w;
        if (pos < 5 && id[pos] == w) pos++;
        __syncthreads();
    }
    // neigh = mean of 5 nearest anchors (nearest-first summation order)
    for (int c = threadIdx.x; c < DD_; c += 256) {
        float s = 0.f;
        #pragma unroll
        for (int k = 0; k < 5; k++) s += anchors[(size_t)winners[k] * DD_ + c];
        g_neigh[(size_t)n * DD_ + c] = s * 0.2f;
    }
}

// ---------------- BN: deterministic two-stage column stats ----------------
__global__ __launch_bounds__(256) void bn_stats_kernel(const float* __restrict__ X) {
    int b = blockIdx.x;                   // 128 blocks, 128 rows each
    int c0 = threadIdx.x, c1 = threadIdx.x + 256;
    float s0 = 0, q0 = 0, s1 = 0, q1 = 0;
    const float* p = X + (size_t)b * 128 * DD_;
    for (int r = 0; r < 128; r++) {
        float x0 = p[(size_t)r * DD_ + c0];
        float x1 = p[(size_t)r * DD_ + c1];
        s0 += x0; q0 += x0 * x0;
        s1 += x1; q1 += x1 * x1;
    }
    g_part[b * DD_ + c0] = s0;
    g_part[b * DD_ + c1] = s1;
    g_part[128 * DD_ + b * DD_ + c0] = q0;
    g_part[128 * DD_ + b * DD_ + c1] = q1;
}

__global__ void bn_finalize_kernel(const float* __restrict__ g,
                                   const float* __restrict__ bt) {
    int c = blockIdx.x * 256 + threadIdx.x;  // 2 blocks x 256 = 512
    float s = 0, q = 0;
    for (int b = 0; b < 128; b++) {
        s += g_part[b * DD_ + c];
        q += g_part[128 * DD_ + b * DD_ + c];
    }
    float mu = s * (1.0f / NN_);
    float var = q * (1.0f / NN_) - mu * mu;
    float sc = g[c] * rsqrtf(var + 1e-5f);
    g_scale[c] = sc;
    g_shift[c] = bt[c] - mu * sc;
}

template <bool TANH>
__global__ void bn_apply_kernel(const float* __restrict__ X, float* __restrict__ Y) {
    size_t i = ((size_t)blockIdx.x * 256 + threadIdx.x) * 4;
    int c = (int)(i & (DD_ - 1));
    float4 x  = *reinterpret_cast<const float4*>(X + i);
    float4 sc = *reinterpret_cast<const float4*>(g_scale + c);
    float4 sh = *reinterpret_cast<const float4*>(g_shift + c);
    float4 y;
    y.x = x.x * sc.x + sh.x; y.y = x.y * sc.y + sh.y;
    y.z = x.z * sc.z + sh.z; y.w = x.w * sc.w + sh.w;
    if (TANH) { y.x = tanhf(y.x); y.y = tanhf(y.y); y.z = tanhf(y.z); y.w = tanhf(y.w); }
    *reinterpret_cast<float4*>(Y + i) = y;
}

// ---------------- pack src into left half of concat buffer ----------------
__global__ void pack_src_kernel(const float* __restrict__ src) {
    size_t idx = ((size_t)blockIdx.x * 256 + threadIdx.x) * 4;  // over NN_*DD_
    size_t r = idx >> 9;
    int c = (int)(idx & 511);
    *reinterpret_cast<float4*>(g_cat + r * 1024 + c) =
        *reinterpret_cast<const float4*>(src + idx);
}

// ---------------- launch ----------------
static float* symAddr(const void* symbol) {
    void* p = nullptr;
    cudaGetSymbolAddress(&p, symbol);
    return (float*)p;
}

extern "C" void kernel_launch(void* const* d_in, const int* in_sizes, int n_in,
                              void* d_out, int out_size) {
    (void)in_sizes; (void)n_in; (void)out_size;
    const float* src    = (const float*)d_in[0];
    const float* anchor = (const float*)d_in[1];
    const float* W_dim  = (const float*)d_in[2];
    const float* b_dim  = (const float*)d_in[3];
    const float* W_fus  = (const float*)d_in[4];
    const float* b_fus  = (const float*)d_in[5];
    const float* W_e1   = (const float*)d_in[6];
    const float* b_e1   = (const float*)d_in[7];
    const float* W_e2   = (const float*)d_in[8];
    const float* b_e2   = (const float*)d_in[9];
    const float* g1     = (const float*)d_in[10];
    const float* bt1    = (const float*)d_in[11];
    const float* g2     = (const float*)d_in[12];
    const float* bt2    = (const float*)d_in[13];
    const float* W_d    = (const float*)d_in[14];
    const float* b_d    = (const float*)d_in[15];
    const float* g_d    = (const float*)d_in[16];
    const float* bt_d   = (const float*)d_in[17];
    float* out = (float*)d_out;

    float* pS     = symAddr(g_S);
    float* pNeigh = symAddr(g_neigh);
    float* pCat   = symAddr(g_cat);
    float* pComb  = symAddr(g_comb);
    float* pCombn = symAddr(g_combn);
    float* pH     = symAddr(g_h);
    float* pR     = symAddr(g_r);
    float* pComb2 = symAddr(g_comb2);
    float* pDec   = symAddr(g_dec);

    const int T = 256;

    // 1) anchor norms
    anorm_kernel<<<MM_ / 8, T>>>(anchor);

    // 2) S = src @ anchor^T   [16384 x 8192], K=512
    gemm_kernel<true, 0><<<dim3(MM_ / 128, NN_ / 128), T>>>(
        src, anchor, nullptr, nullptr, pS, DD_, DD_, DD_, MM_);

    // 3) top-5 + neighbor mean
    topk_kernel<<<NN_, T>>>(anchor);

    // 4) concat buffer: left = src, right = neigh @ W_dim + b_dim
    pack_src_kernel<<<(NN_ * DD_ / 4) / T, T>>>(src);
    gemm_kernel<false, 1><<<dim3(DD_ / 128, NN_ / 128), T>>>(
        pNeigh, W_dim, b_dim, nullptr, pCat + DD_, DD_, DD_, DD_, 2 * DD_);

    // 5) comb = cat @ W_fus + b_fus   (K=1024)
    gemm_kernel<false, 1><<<dim3(DD_ / 128, NN_ / 128), T>>>(
        pCat, W_fus, b_fus, nullptr, pComb, 2 * DD_, 2 * DD_, DD_, DD_);

    // 6) BN1
    bn_stats_kernel<<<128, T>>>(pComb);
    bn_finalize_kernel<<<2, T>>>(g1, bt1);
    bn_apply_kernel<false><<<(NN_ * DD_ / 4) / T, T>>>(pComb, pCombn);

    // 7) h = tanh(combn @ W_e1 + b_e1)   [16384 x 2048]
    gemm_kernel<false, 2><<<dim3(FF_ / 128, NN_ / 128), T>>>(
        pCombn, W_e1, b_e1, nullptr, pH, DD_, DD_, FF_, FF_);

    // 8) r = combn + (h @ W_e2 + b_e2)   (K=2048)
    gemm_kernel<false, 3><<<dim3(DD_ / 128, NN_ / 128), T>>>(
        pH, W_e2, b_e2, pCombn, pR, FF_, FF_, DD_, DD_);

    // 9) BN2
    bn_stats_kernel<<<128, T>>>(pR);
    bn_finalize_kernel<<<2, T>>>(g2, bt2);
    bn_apply_kernel<false><<<(NN_ * DD_ / 4) / T, T>>>(pR, pComb2);

    // 10) dec = comb2 @ W_d + b_d
    gemm_kernel<false, 1><<<dim3(DD_ / 128, NN_ / 128), T>>>(
        pComb2, W_d, b_d, nullptr, pDec, DD_, DD_, DD_, DD_);

    // 11) out = tanh(BN(dec))
    bn_stats_kernel<<<128, T>>>(pDec);
    bn_finalize_kernel<<<2, T>>>(g_d, bt_d);
    bn_apply_kernel<true><<<(NN_ * DD_ / 4) / T, T>>>(pDec, out);
}

// round 6
// speedup vs baseline: 1.0859x; 1.0859x over previous
#include <cuda_runtime.h>
#include <cuda_bf16.h>
#include <math.h>

// Problem constants
#define NN_ 16384
#define MM_ 8192
#define DD_ 512
#define FF_ 2048

// ---------------- static scratch (no runtime allocation allowed) ----------------
__device__ float g_anorm[MM_];
__device__ float g_S[(size_t)NN_ * MM_];          // 512 MB: coarse src @ anchor^T
__device__ __nv_bfloat16 g_src_bf[(size_t)NN_ * DD_];
__device__ __nv_bfloat16 g_anch_bf[(size_t)MM_ * DD_];
__device__ float g_neigh[(size_t)NN_ * DD_];
__device__ float g_cat[(size_t)NN_ * 2 * DD_];    // [src | a_map]
__device__ float g_comb[(size_t)NN_ * DD_];
__device__ float g_combn[(size_t)NN_ * DD_];
__device__ float g_h[(size_t)NN_ * FF_];          // 128 MB
__device__ float g_r[(size_t)NN_ * DD_];
__device__ float g_comb2[(size_t)NN_ * DD_];
__device__ float g_dec[(size_t)NN_ * DD_];
__device__ float g_part[2 * 128 * DD_];           // BN partial sums
__device__ float g_scale[DD_];
__device__ float g_shift[DD_];

// ---------------- fp32 -> bf16 conversion ----------------
__global__ void tobf16_kernel(const float* __restrict__ X, __nv_bfloat16* __restrict__ Y) {
    size_t i = ((size_t)blockIdx.x * 256 + threadIdx.x) * 4;
    float4 x = *reinterpret_cast<const float4*>(X + i);
    __nv_bfloat162 lo = __floats2bfloat162_rn(x.x, x.y);
    __nv_bfloat162 hi = __floats2bfloat162_rn(x.z, x.w);
    uint2 p;
    p.x = *reinterpret_cast<unsigned*>(&lo);
    p.y = *reinterpret_cast<unsigned*>(&hi);
    *reinterpret_cast<uint2*>(Y + i) = p;
}

// ---------------- anchor squared norms ----------------
__global__ void anorm_kernel(const float* __restrict__ A) {
    int warp = threadIdx.x >> 5, lane = threadIdx.x & 31;
    int row = blockIdx.x * 8 + warp;
    const float* p = A + (size_t)row * DD_;
    float s = 0.f;
    for (int c = lane; c < DD_; c += 32) { float v = p[c]; s += v * v; }
    #pragma unroll
    for (int o = 16; o; o >>= 1) s += __shfl_xor_sync(0xffffffffu, s, o);
    if (lane == 0) g_anorm[row] = s;
}

// ---------------- bf16 tensor-core GEMM (NT): C = A[rowsxK] * B[colsxK]^T ----------------
// 128x128x32 tiles, 8 warps (2x4), warp tile 64x32, mma.m16n8k16, fp32 accum.
#define LDS_BF 40   // padded smem row stride in bf16 elems (80B, conflict-free ldmatrix)

__global__ __launch_bounds__(256) void gemm_bf16_nt(
    const __nv_bfloat16* __restrict__ A, const __nv_bfloat16* __restrict__ B,
    float* __restrict__ C, int K, int lda, int ldb, int ldc)
{
    __shared__ __nv_bfloat16 As[2][128 * LDS_BF];
    __shared__ __nv_bfloat16 Bs[2][128 * LDS_BF];
    const int tid = threadIdx.x;
    const int lane = tid & 31, w = tid >> 5;
    const int wr = w >> 2, wc = w & 3;              // 2 x 4 warp grid
    const int rowBase = blockIdx.y * 128;
    const int colBase = blockIdx.x * 128;

    float acc[4][4][4];
    #pragma unroll
    for (int i = 0; i < 4; i++)
        #pragma unroll
        for (int j = 0; j < 4; j++)
            #pragma unroll
            for (int k = 0; k < 4; k++) acc[i][j][k] = 0.f;

    const int KT = K / 32;

    // tile loader: 128 rows x 32 bf16 = 512 x 16B chunks per matrix
    #define ISSUE_TILE(kt, buf)                                                    \
    {                                                                              \
        int k0 = (kt) * 32;                                                        \
        _Pragma("unroll")                                                          \
        for (int i = 0; i < 2; i++) {                                              \
            int v = tid + i * 256;                                                 \
            int r = v >> 2, c8 = (v & 3) * 8;                                      \
            unsigned sa = (unsigned)__cvta_generic_to_shared(                      \
                &As[buf][r * LDS_BF + c8]);                                        \
            const __nv_bfloat16* ga = A + (size_t)(rowBase + r) * lda + k0 + c8;   \
            asm volatile("cp.async.ca.shared.global [%0], [%1], 16;\n"             \
                         :: "r"(sa), "l"(ga));                                     \
            unsigned sb = (unsigned)__cvta_generic_to_shared(                      \
                &Bs[buf][r * LDS_BF + c8]);                                        \
            const __nv_bfloat16* gb = B + (size_t)(colBase + r) * ldb + k0 + c8;   \
            asm volatile("cp.async.ca.shared.global [%0], [%1], 16;\n"             \
                         :: "r"(sb), "l"(gb));                                     \
        }                                                                          \
        asm volatile("cp.async.commit_group;\n");                                  \
    }

    ISSUE_TILE(0, 0);

    for (int kt = 0; kt < KT; kt++) {
        int buf = kt & 1;
        if (kt + 1 < KT) { ISSUE_TILE(kt + 1, buf ^ 1); }
        else            { asm volatile("cp.async.commit_group;\n"); }
        asm volatile("cp.async.wait_group 1;\n");
        __syncthreads();

        #pragma unroll
        for (int ks = 0; ks < 2; ks++) {
            unsigned a[4][4], b[4][2];
            #pragma unroll
            for (int mt = 0; mt < 4; mt++) {
                int r = wr * 64 + mt * 16 + (lane & 15);
                int c = ks * 16 + (lane >> 4) * 8;
                unsigned addr = (unsigned)__cvta_generic_to_shared(
                    &As[buf][r * LDS_BF + c]);
                asm volatile(
                    "ldmatrix.sync.aligned.m8n8.x4.shared.b16 {%0,%1,%2,%3}, [%4];\n"
                    : "=r"(a[mt][0]), "=r"(a[mt][1]), "=r"(a[mt][2]), "=r"(a[mt][3])
                    : "r"(addr));
            }
            #pragma unroll
            for (int nt = 0; nt < 4; nt++) {
                int r = wc * 32 + nt * 8 + (lane & 7);
                int c = ks * 16 + ((lane >> 3) & 1) * 8;
                unsigned addr = (unsigned)__cvta_generic_to_shared(
                    &Bs[buf][r * LDS_BF + c]);
                asm volatile(
                    "ldmatrix.sync.aligned.m8n8.x2.shared.b16 {%0,%1}, [%2];\n"
                    : "=r"(b[nt][0]), "=r"(b[nt][1]) : "r"(addr));
            }
            #pragma unroll
            for (int mt = 0; mt < 4; mt++)
                #pragma unroll
                for (int nt = 0; nt < 4; nt++) {
                    float* c = acc[mt][nt];
                    asm volatile(
                        "mma.sync.aligned.m16n8k16.row.col.f32.bf16.bf16.f32 "
                        "{%0,%1,%2,%3}, {%4,%5,%6,%7}, {%8,%9}, {%0,%1,%2,%3};\n"
                        : "+f"(c[0]), "+f"(c[1]), "+f"(c[2]), "+f"(c[3])
                        : "r"(a[mt][0]), "r"(a[mt][1]), "r"(a[mt][2]), "r"(a[mt][3]),
                          "r"(b[nt][0]), "r"(b[nt][1]));
                }
        }
        __syncthreads();
    }

    #pragma unroll
    for (int mt = 0; mt < 4; mt++) {
        int row0 = rowBase + wr * 64 + mt * 16 + (lane >> 2);
        #pragma unroll
        for (int nt = 0; nt < 4; nt++) {
            int col = colBase + wc * 32 + nt * 8 + (lane & 3) * 2;
            float2 v0 = make_float2(acc[mt][nt][0], acc[mt][nt][1]);
            float2 v1 = make_float2(acc[mt][nt][2], acc[mt][nt][3]);
            *reinterpret_cast<float2*>(C + (size_t)row0 * ldc + col) = v0;
            *reinterpret_cast<float2*>(C + (size_t)(row0 + 8) * ldc + col) = v1;
        }
    }
    #undef ISSUE_TILE
}

// ---------------- generic tiled fp32 SGEMM (dense layers) ----------------
// C[row, col] = sum_k A[row,k] * (BT ? B[col,k] : B[k,col])  (+ epilogue)
// EPI: 0 = none, 1 = +bias, 2 = tanh(+bias), 3 = +bias +res
template <bool BT, int EPI>
__global__ __launch_bounds__(256) void gemm_kernel(
    const float* __restrict__ A, const float* __restrict__ B,
    const float* __restrict__ bias, const float* __restrict__ res,
    float* __restrict__ C, int K, int lda, int ldb, int ldc)
{
    __shared__ float As[16][128];
    __shared__ float Bs[16][128];
    const int tid = threadIdx.x;
    const int tcol = tid & 15, trow = tid >> 4;
    const int rowBase = blockIdx.y * 128;
    const int colBase = blockIdx.x * 128;

    float acc[8][8];
    #pragma unroll
    for (int i = 0; i < 8; i++)
        #pragma unroll
        for (int j = 0; j < 8; j++) acc[i][j] = 0.f;

    for (int k0 = 0; k0 < K; k0 += 16) {
        #pragma unroll
        for (int t = 0; t < 2; t++) {
            int v = tid + t * 256;
            int r = v >> 2, c4 = (v & 3) << 2;
            float4 a4 = *reinterpret_cast<const float4*>(
                A + (size_t)(rowBase + r) * lda + (k0 + c4));
            As[c4 + 0][r] = a4.x; As[c4 + 1][r] = a4.y;
            As[c4 + 2][r] = a4.z; As[c4 + 3][r] = a4.w;
            if (BT) {
                float4 b4 = *reinterpret_cast<const float4*>(
                    B + (size_t)(colBase + r) * ldb + (k0 + c4));
                Bs[c4 + 0][r] = b4.x; Bs[c4 + 1][r] = b4.y;
                Bs[c4 + 2][r] = b4.z; Bs[c4 + 3][r] = b4.w;
            } else {
                int br = v >> 5, bc = (v & 31) << 2;
                float4 b4 = *reinterpret_cast<const float4*>(
                    B + (size_t)(k0 + br) * ldb + (colBase + bc));
                *reinterpret_cast<float4*>(&Bs[br][bc]) = b4;
            }
        }
        __syncthreads();
        #pragma unroll
        for (int k = 0; k < 16; k++) {
            float ra[8], rb[8];
            #pragma unroll
            for (int i = 0; i < 8; i++) ra[i] = As[k][trow * 8 + i];
            #pragma unroll
            for (int j = 0; j < 8; j++) rb[j] = Bs[k][tcol * 8 + j];
            #pragma unroll
            for (int i = 0; i < 8; i++)
                #pragma unroll
                for (int j = 0; j < 8; j++) acc[i][j] += ra[i] * rb[j];
        }
        __syncthreads();
    }

    #pragma unroll
    for (int i = 0; i < 8; i++) {
        int row = rowBase + trow * 8 + i;
        #pragma unroll
        for (int j = 0; j < 8; j += 4) {
            int col = colBase + tcol * 8 + j;
            float4 v;
            v.x = acc[i][j + 0]; v.y = acc[i][j + 1];
            v.z = acc[i][j + 2]; v.w = acc[i][j + 3];
            if (EPI >= 1) {
                v.x += bias[col + 0]; v.y += bias[col + 1];
                v.z += bias[col + 2]; v.w += bias[col + 3];
            }
            if (EPI == 2) {
                v.x = tanhf(v.x); v.y = tanhf(v.y);
                v.z = tanhf(v.z); v.w = tanhf(v.w);
            }
            if (EPI == 3) {
                float4 rr = *reinterpret_cast<const float4*>(
                    res + (size_t)row * ldc + col);
                v.x += rr.x; v.y += rr.y; v.z += rr.z; v.w += rr.w;
            }
            *reinterpret_cast<float4*>(C + (size_t)row * ldc + col) = v;
        }
    }
}

// ---------------- coarse top-16 -> exact fp32 rescore -> top-5 + mean ----------------
// Coarse: d = anorm[m] - 2*S_bf16[n,m] (per-row ||src||^2 is rank-invariant).
// bf16 coarse error (~0.4 in d^2) vs rank5->rank16 true margin (~18): recall is safe.
// Exact rescore reproduces the fp32 ranking arithmetic (anorm - 2*fp32 dot).
__global__ __launch_bounds__(256) void topk16_kernel(
    const float* __restrict__ src, const float* __restrict__ anchors)
{
    int n = blockIdx.x;
    int tid = threadIdx.x;
    int lane = tid & 31, w = tid >> 5;
    const float* Srow = g_S + (size_t)n * MM_;

    float v[16]; int id[16];
    #pragma unroll
    for (int i = 0; i < 16; i++) { v[i] = 3.4e38f; id[i] = 0x7fffffff; }
    for (int m = tid; m < MM_; m += 256) {
        float d = g_anorm[m] - 2.0f * Srow[m];
        if (d < v[15] || (d == v[15] && m < id[15])) {
            int p = 15;
            while (p > 0 && (d < v[p-1] || (d == v[p-1] && m < id[p-1]))) {
                v[p] = v[p-1]; id[p] = id[p-1]; p--;
            }
            v[p] = d; id[p] = m;
        }
    }

    __shared__ float sv[256];
    __shared__ int   si[256];
    __shared__ int   cand[16];
    int pos = 0;
    for (int round = 0; round < 16; round++) {
        sv[tid] = (pos < 16) ? v[pos] : 3.4e38f;
        si[tid] = (pos < 16) ? id[pos] : 0x7fffffff;
        __syncthreads();
        for (int s = 128; s > 0; s >>= 1) {
            if (tid < s) {
                float ov = sv[tid + s]; int oi = si[tid + s];
                if (ov < sv[tid] || (ov == sv[tid] && oi < si[tid])) {
                    sv[tid] = ov; si[tid] = oi;
                }
            }
            __syncthreads();
        }
        int wnr = si[0];
        if (tid == 0) cand[round] = wnr;
        if (pos < 16 && id[pos] == wnr) pos++;
        __syncthreads();
    }

    // exact fp32 rescore of 16 candidates (8 warps x 2 candidates)
    __shared__ float dex[16];
    const float* srow = src + (size_t)n * DD_;
    for (int c = w; c < 16; c += 8) {
        int m = cand[c];
        const float* a = anchors + (size_t)m * DD_;
        float s = 0.f;
        for (int i = lane; i < DD_; i += 32) s += srow[i] * a[i];
        #pragma unroll
        for (int o = 16; o; o >>= 1) s += __shfl_xor_sync(0xffffffffu, s, o);
        if (lane == 0) dex[c] = g_anorm[m] - 2.0f * s;
    }
    __syncthreads();

    __shared__ int win5[5];
    if (tid == 0) {
        bool used[16];
        #pragma unroll
        for (int i = 0; i < 16; i++) used[i] = false;
        for (int r2 = 0; r2 < 5; r2++) {
            float bv = 3.4e38f; int bi = 0x7fffffff; int bc = 0;
            for (int c = 0; c < 16; c++) {
                if (used[c]) continue;
                if (dex[c] < bv || (dex[c] == bv && cand[c] < bi)) {
                    bv = dex[c]; bi = cand[c]; bc = c;
                }
            }
            used[bc] = true; win5[r2] = bi;
        }
    }
    __syncthreads();

    for (int c = tid; c < DD_; c += 256) {
        float s = 0.f;
        #pragma unroll
        for (int k = 0; k < 5; k++) s += anchors[(size_t)win5[k] * DD_ + c];
        g_neigh[(size_t)n * DD_ + c] = s * 0.2f;
    }
}

// ---------------- BN: deterministic two-stage column stats ----------------
__global__ __launch_bounds__(256) void bn_stats_kernel(const float* __restrict__ X) {
    int b = blockIdx.x;                   // 128 blocks, 128 rows each
    int c0 = threadIdx.x, c1 = threadIdx.x + 256;
    float s0 = 0, q0 = 0, s1 = 0, q1 = 0;
    const float* p = X + (size_t)b * 128 * DD_;
    for (int r = 0; r < 128; r++) {
        float x0 = p[(size_t)r * DD_ + c0];
        float x1 = p[(size_t)r * DD_ + c1];
        s0 += x0; q0 += x0 * x0;
        s1 += x1; q1 += x1 * x1;
    }
    g_part[b * DD_ + c0] = s0;
    g_part[b * DD_ + c1] = s1;
    g_part[128 * DD_ + b * DD_ + c0] = q0;
    g_part[128 * DD_ + b * DD_ + c1] = q1;
}

__global__ void bn_finalize_kernel(const float* __restrict__ g,
                                   const float* __restrict__ bt) {
    int c = blockIdx.x * 256 + threadIdx.x;  // 2 blocks x 256 = 512
    float s = 0, q = 0;
    for (int b = 0; b < 128; b++) {
        s += g_part[b * DD_ + c];
        q += g_part[128 * DD_ + b * DD_ + c];
    }
    float mu = s * (1.0f / NN_);
    float var = q * (1.0f / NN_) - mu * mu;
    float sc = g[c] * rsqrtf(var + 1e-5f);
    g_scale[c] = sc;
    g_shift[c] = bt[c] - mu * sc;
}

template <bool TANH>
__global__ void bn_apply_kernel(const float* __restrict__ X, float* __restrict__ Y) {
    size_t i = ((size_t)blockIdx.x * 256 + threadIdx.x) * 4;
    int c = (int)(i & (DD_ - 1));
    float4 x  = *reinterpret_cast<const float4*>(X + i);
    float4 sc = *reinterpret_cast<const float4*>(g_scale + c);
    float4 sh = *reinterpret_cast<const float4*>(g_shift + c);
    float4 y;
    y.x = x.x * sc.x + sh.x; y.y = x.y * sc.y + sh.y;
    y.z = x.z * sc.z + sh.z; y.w = x.w * sc.w + sh.w;
    if (TANH) { y.x = tanhf(y.x); y.y = tanhf(y.y); y.z = tanhf(y.z); y.w = tanhf(y.w); }
    *reinterpret_cast<float4*>(Y + i) = y;
}

// ---------------- pack src into left half of concat buffer ----------------
__global__ void pack_src_kernel(const float* __restrict__ src) {
    size_t idx = ((size_t)blockIdx.x * 256 + threadIdx.x) * 4;  // over NN_*DD_
    size_t r = idx >> 9;
    int c = (int)(idx & 511);
    *reinterpret_cast<float4*>(g_cat + r * 1024 + c) =
        *reinterpret_cast<const float4*>(src + idx);
}

// ---------------- launch ----------------
static float* symAddr(const void* symbol) {
    void* p = nullptr;
    cudaGetSymbolAddress(&p, symbol);
    return (float*)p;
}

extern "C" void kernel_launch(void* const* d_in, const int* in_sizes, int n_in,
                              void* d_out, int out_size) {
    (void)in_sizes; (void)n_in; (void)out_size;
    const float* src    = (const float*)d_in[0];
    const float* anchor = (const float*)d_in[1];
    const float* W_dim  = (const float*)d_in[2];
    const float* b_dim  = (const float*)d_in[3];
    const float* W_fus  = (const float*)d_in[4];
    const float* b_fus  = (const float*)d_in[5];
    const float* W_e1   = (const float*)d_in[6];
    const float* b_e1   = (const float*)d_in[7];
    const float* W_e2   = (const float*)d_in[8];
    const float* b_e2   = (const float*)d_in[9];
    const float* g1     = (const float*)d_in[10];
    const float* bt1    = (const float*)d_in[11];
    const float* g2     = (const float*)d_in[12];
    const float* bt2    = (const float*)d_in[13];
    const float* W_d    = (const float*)d_in[14];
    const float* b_d    = (const float*)d_in[15];
    const float* g_d    = (const float*)d_in[16];
    const float* bt_d   = (const float*)d_in[17];
    float* out = (float*)d_out;

    float* pS     = symAddr(g_S);
    float* pNeigh = symAddr(g_neigh);
    float* pCat   = symAddr(g_cat);
    float* pComb  = symAddr(g_comb);
    float* pCombn = symAddr(g_combn);
    float* pH     = symAddr(g_h);
    float* pR     = symAddr(g_r);
    float* pComb2 = symAddr(g_comb2);
    float* pDec   = symAddr(g_dec);
    __nv_bfloat16* pSrcBf  = (__nv_bfloat16*)symAddr(g_src_bf);
    __nv_bfloat16* pAnchBf = (__nv_bfloat16*)symAddr(g_anch_bf);

    const int T = 256;

    // 0) bf16 copies of src / anchors for the coarse distance GEMM
    tobf16_kernel<<<(NN_ * DD_ / 4) / T, T>>>(src, pSrcBf);
    tobf16_kernel<<<(MM_ * DD_ / 4) / T, T>>>(anchor, pAnchBf);

    // 1) anchor norms (fp32)
    anorm_kernel<<<MM_ / 8, T>>>(anchor);

    // 2) coarse S = src_bf @ anchor_bf^T   [16384 x 8192], K=512, tensor cores
    gemm_bf16_nt<<<dim3(MM_ / 128, NN_ / 128), T>>>(
        pSrcBf, pAnchBf, pS, DD_, DD_, DD_, MM_);

    // 3) top-16 candidates -> exact fp32 rescore -> top-5 + neighbor mean
    topk16_kernel<<<NN_, T>>>(src, anchor);

    // 4) concat buffer: left = src, right = neigh @ W_dim + b_dim
    pack_src_kernel<<<(NN_ * DD_ / 4) / T, T>>>(src);
    gemm_kernel<false, 1><<<dim3(DD_ / 128, NN_ / 128), T>>>(
        pNeigh, W_dim, b_dim, nullptr, pCat + DD_, DD_, DD_, DD_, 2 * DD_);

    // 5) comb = cat @ W_fus + b_fus   (K=1024)
    gemm_kernel<false, 1><<<dim3(DD_ / 128, NN_ / 128), T>>>(
        pCat, W_fus, b_fus, nullptr, pComb, 2 * DD_, 2 * DD_, DD_, DD_);

    // 6) BN1
    bn_stats_kernel<<<128, T>>>(pComb);
    bn_finalize_kernel<<<2, T>>>(g1, bt1);
    bn_apply_kernel<false><<<(NN_ * DD_ / 4) / T, T>>>(pComb, pCombn);

    // 7) h = tanh(combn @ W_e1 + b_e1)   [16384 x 2048]
    gemm_kernel<false, 2><<<dim3(FF_ / 128, NN_ / 128), T>>>(
        pCombn, W_e1, b_e1, nullptr, pH, DD_, DD_, FF_, FF_);

    // 8) r = combn + (h @ W_e2 + b_e2)   (K=2048)
    gemm_kernel<false, 3><<<dim3(DD_ / 128, NN_ / 128), T>>>(
        pH, W_e2, b_e2, pCombn, pR, FF_, FF_, DD_, DD_);

    // 9) BN2
    bn_stats_kernel<<<128, T>>>(pR);
    bn_finalize_kernel<<<2, T>>>(g2, bt2);
    bn_apply_kernel<false><<<(NN_ * DD_ / 4) / T, T>>>(pR, pComb2);

    // 10) dec = comb2 @ W_d + b_d
    gemm_kernel<false, 1><<<dim3(DD_ / 128, NN_ / 128), T>>>(
        pComb2, W_d, b_d, nullptr, pDec, DD_, DD_, DD_, DD_);

    // 11) out = tanh(BN(dec))
    bn_stats_kernel<<<128, T>>>(pDec);
    bn_finalize_kernel<<<2, T>>>(g_d, bt_d);
    bn_apply_kernel<true><<<(NN_ * DD_ / 4) / T, T>>>(pDec, out);
}

// round 7
// speedup vs baseline: 1.3939x; 1.2837x over previous
#include <cuda_runtime.h>
#include <cuda_bf16.h>
#include <math.h>

// Problem constants
#define NN_ 16384
#define MM_ 8192
#define DD_ 512
#define FF_ 2048

// ---------------- static scratch (no runtime allocation allowed) ----------------
__device__ float g_anorm[MM_];
__device__ float g_S[(size_t)NN_ * MM_];          // 512 MB: coarse src @ anchor^T
__device__ __nv_bfloat16 g_src_bf[(size_t)NN_ * DD_];
__device__ __nv_bfloat16 g_anch_bf[(size_t)MM_ * DD_];

// split activations (hi/lo bf16)
__device__ __nv_bfloat16 g_neigh_hi[(size_t)NN_ * DD_];
__device__ __nv_bfloat16 g_neigh_lo[(size_t)NN_ * DD_];
__device__ __nv_bfloat16 g_cat_hi[(size_t)NN_ * 2 * DD_];
__device__ __nv_bfloat16 g_cat_lo[(size_t)NN_ * 2 * DD_];
__device__ __nv_bfloat16 g_combn_hi[(size_t)NN_ * DD_];
__device__ __nv_bfloat16 g_combn_lo[(size_t)NN_ * DD_];
__device__ __nv_bfloat16 g_h_hi[(size_t)NN_ * FF_];
__device__ __nv_bfloat16 g_h_lo[(size_t)NN_ * FF_];
__device__ __nv_bfloat16 g_c2_hi[(size_t)NN_ * DD_];
__device__ __nv_bfloat16 g_c2_lo[(size_t)NN_ * DD_];

// fp32 intermediates
__device__ float g_comb[(size_t)NN_ * DD_];
__device__ float g_combn[(size_t)NN_ * DD_];      // fp32 kept for residual add
__device__ float g_r[(size_t)NN_ * DD_];
__device__ float g_dec[(size_t)NN_ * DD_];

// transposed + split weights (Wt[n][k] = W[k][n])
__device__ __nv_bfloat16 g_WdimT_hi[DD_ * DD_];
__device__ __nv_bfloat16 g_WdimT_lo[DD_ * DD_];
__device__ __nv_bfloat16 g_WfusT_hi[DD_ * 2 * DD_];
__device__ __nv_bfloat16 g_WfusT_lo[DD_ * 2 * DD_];
__device__ __nv_bfloat16 g_We1T_hi[(size_t)FF_ * DD_];
__device__ __nv_bfloat16 g_We1T_lo[(size_t)FF_ * DD_];
__device__ __nv_bfloat16 g_We2T_hi[(size_t)DD_ * FF_];
__device__ __nv_bfloat16 g_We2T_lo[(size_t)DD_ * FF_];
__device__ __nv_bfloat16 g_WdT_hi[DD_ * DD_];
__device__ __nv_bfloat16 g_WdT_lo[DD_ * DD_];

// BN
__device__ float g_part[2 * 128 * DD_];
__device__ float g_scale[DD_];
__device__ float g_shift[DD_];

// ---------------- helpers ----------------
__device__ __forceinline__ void split2(float x, float y,
                                       __nv_bfloat162& hi, __nv_bfloat162& lo) {
    hi = __floats2bfloat162_rn(x, y);
    float rx = x - __bfloat162float(hi.x);
    float ry = y - __bfloat162float(hi.y);
    lo = __floats2bfloat162_rn(rx, ry);
}

// ---------------- fp32 -> bf16 conversion (single, for distance GEMM) ----------------
__global__ void tobf16_kernel(const float* __restrict__ X, __nv_bfloat16* __restrict__ Y) {
    size_t i = ((size_t)blockIdx.x * 256 + threadIdx.x) * 4;
    float4 x = *reinterpret_cast<const float4*>(X + i);
    __nv_bfloat162 lo = __floats2bfloat162_rn(x.x, x.y);
    __nv_bfloat162 hi = __floats2bfloat162_rn(x.z, x.w);
    uint2 p;
    p.x = *reinterpret_cast<unsigned*>(&lo);
    p.y = *reinterpret_cast<unsigned*>(&hi);
    *reinterpret_cast<uint2*>(Y + i) = p;
}

// ---------------- src -> split bf16 into left half of concat ----------------
__global__ void pack_split_kernel(const float* __restrict__ src) {
    size_t i = ((size_t)blockIdx.x * 256 + threadIdx.x) * 4;   // over NN_*DD_
    size_t r = i >> 9;
    int c = (int)(i & 511);
    float4 x = *reinterpret_cast<const float4*>(src + i);
    __nv_bfloat162 h0, l0, h1, l1;
    split2(x.x, x.y, h0, l0);
    split2(x.z, x.w, h1, l1);
    uint2 ph, pl;
    ph.x = *reinterpret_cast<unsigned*>(&h0); ph.y = *reinterpret_cast<unsigned*>(&h1);
    pl.x = *reinterpret_cast<unsigned*>(&l0); pl.y = *reinterpret_cast<unsigned*>(&l1);
    *reinterpret_cast<uint2*>(g_cat_hi + r * 1024 + c) = ph;
    *reinterpret_cast<uint2*>(g_cat_lo + r * 1024 + c) = pl;
}

// ---------------- weight transpose + split: Thi/Tlo[n][k] = split(W[k][n]) ----------------
__global__ void tsplit_kernel(const float* __restrict__ W,
                              __nv_bfloat16* __restrict__ Thi,
                              __nv_bfloat16* __restrict__ Tlo, int K, int N) {
    __shared__ float tile[32][33];
    int n0 = blockIdx.x * 32, k0 = blockIdx.y * 32;
    int tx = threadIdx.x, ty = threadIdx.y;
    #pragma unroll
    for (int i = 0; i < 4; i++)
        tile[ty + i * 8][tx] = W[(size_t)(k0 + ty + i * 8) * N + n0 + tx];
    __syncthreads();
    #pragma unroll
    for (int i = 0; i < 4; i++) {
        int n = n0 + ty + i * 8;
        float v = tile[tx][ty + i * 8];
        __nv_bfloat16 h = __float2bfloat16(v);
        __nv_bfloat16 l = __float2bfloat16(v - __bfloat162float(h));
        Thi[(size_t)n * K + k0 + tx] = h;
        Tlo[(size_t)n * K + k0 + tx] = l;
    }
}

// ---------------- anchor squared norms ----------------
__global__ void anorm_kernel(const float* __restrict__ A) {
    int warp = threadIdx.x >> 5, lane = threadIdx.x & 31;
    int row = blockIdx.x * 8 + warp;
    const float* p = A + (size_t)row * DD_;
    float s = 0.f;
    for (int c = lane; c < DD_; c += 32) { float v = p[c]; s += v * v; }
    #pragma unroll
    for (int o = 16; o; o >>= 1) s += __shfl_xor_sync(0xffffffffu, s, o);
    if (lane == 0) g_anorm[row] = s;
}

// ---------------- bf16 tensor-core GEMM (NT), multi-pass hi/lo ----------------
// NPASS==1: C = Ahi * Bhi^T
// NPASS==3: C = Ahi*Bhi^T + Alo*Bhi^T + Ahi*Blo^T   (fp32-accurate split product)
// EPI: 0 = fp32 store, 1 = +bias fp32, 2 = +bias tanh -> split bf16,
//      3 = +bias +res fp32, 4 = +bias -> split bf16
#define LDS_BF 40

template <int NPASS, int EPI>
__global__ __launch_bounds__(256) void gemm_bf16_mp(
    const __nv_bfloat16* __restrict__ Ahi, const __nv_bfloat16* __restrict__ Alo,
    const __nv_bfloat16* __restrict__ Bhi, const __nv_bfloat16* __restrict__ Blo,
    const float* __restrict__ bias, const float* __restrict__ res,
    float* __restrict__ C, __nv_bfloat16* __restrict__ Chi,
    __nv_bfloat16* __restrict__ Clo,
    int K, int lda, int ldb, int ldc)
{
    __shared__ __nv_bfloat16 As[2][128 * LDS_BF];
    __shared__ __nv_bfloat16 Bs[2][128 * LDS_BF];
    const int tid = threadIdx.x;
    const int lane = tid & 31, w = tid >> 5;
    const int wr = w >> 2, wc = w & 3;
    const int rowBase = blockIdx.y * 128;
    const int colBase = blockIdx.x * 128;

    float acc[4][4][4];
    #pragma unroll
    for (int i = 0; i < 4; i++)
        #pragma unroll
        for (int j = 0; j < 4; j++)
            #pragma unroll
            for (int k = 0; k < 4; k++) acc[i][j][k] = 0.f;

    const int KT = K / 32;
    const int TT = NPASS * KT;

    #define ISSUE_TILE(t, buf)                                                     \
    {                                                                              \
        int p_ = (t) / KT;                                                         \
        int k0 = ((t) - p_ * KT) * 32;                                             \
        const __nv_bfloat16* Ab = (NPASS == 3 && p_ == 1) ? Alo : Ahi;             \
        const __nv_bfloat16* Bb = (NPASS == 3 && p_ == 2) ? Blo : Bhi;             \
        _Pragma("unroll")                                                          \
        for (int i = 0; i < 2; i++) {                                              \
            int v = tid + i * 256;                                                 \
            int r = v >> 2, c8 = (v & 3) * 8;                                      \
            unsigned sa = (unsigned)__cvta_generic_to_shared(                      \
                &As[buf][r * LDS_BF + c8]);                                        \
            const __nv_bfloat16* ga = Ab + (size_t)(rowBase + r) * lda + k0 + c8;  \
            asm volatile("cp.async.ca.shared.global [%0], [%1], 16;\n"             \
                         :: "r"(sa), "l"(ga));                                     \
            unsigned sb = (unsigned)__cvta_generic_to_shared(                      \
                &Bs[buf][r * LDS_BF + c8]);                                        \
            const __nv_bfloat16* gb = Bb + (size_t)(colBase + r) * ldb + k0 + c8;  \
            asm volatile("cp.async.ca.shared.global [%0], [%1], 16;\n"             \
                         :: "r"(sb), "l"(gb));                                     \
        }                                                                          \
        asm volatile("cp.async.commit_group;\n");                                  \
    }

    ISSUE_TILE(0, 0);

    for (int t = 0; t < TT; t++) {
        int buf = t & 1;
        if (t + 1 < TT) { ISSUE_TILE(t + 1, buf ^ 1); }
        else            { asm volatile("cp.async.commit_group;\n"); }
        asm volatile("cp.async.wait_group 1;\n");
        __syncthreads();

        #pragma unroll
        for (int ks = 0; ks < 2; ks++) {
            unsigned a[4][4], b[4][2];
            #pragma unroll
            for (int mt = 0; mt < 4; mt++) {
                int r = wr * 64 + mt * 16 + (lane & 15);
                int c = ks * 16 + (lane >> 4) * 8;
                unsigned addr = (unsigned)__cvta_generic_to_shared(
                    &As[buf][r * LDS_BF + c]);
                asm volatile(
                    "ldmatrix.sync.aligned.m8n8.x4.shared.b16 {%0,%1,%2,%3}, [%4];\n"
                    : "=r"(a[mt][0]), "=r"(a[mt][1]), "=r"(a[mt][2]), "=r"(a[mt][3])
                    : "r"(addr));
            }
            #pragma unroll
            for (int nt = 0; nt < 4; nt++) {
                int r = wc * 32 + nt * 8 + (lane & 7);
                int c = ks * 16 + ((lane >> 3) & 1) * 8;
                unsigned addr = (unsigned)__cvta_generic_to_shared(
                    &Bs[buf][r * LDS_BF + c]);
                asm volatile(
                    "ldmatrix.sync.aligned.m8n8.x2.shared.b16 {%0,%1}, [%2];\n"
                    : "=r"(b[nt][0]), "=r"(b[nt][1]) : "r"(addr));
            }
            #pragma unroll
            for (int mt = 0; mt < 4; mt++)
                #pragma unroll
                for (int nt = 0; nt < 4; nt++) {
                    float* c = acc[mt][nt];
                    asm volatile(
                        "mma.sync.aligned.m16n8k16.row.col.f32.bf16.bf16.f32 "
                        "{%0,%1,%2,%3}, {%4,%5,%6,%7}, {%8,%9}, {%0,%1,%2,%3};\n"
                        : "+f"(c[0]), "+f"(c[1]), "+f"(c[2]), "+f"(c[3])
                        : "r"(a[mt][0]), "r"(a[mt][1]), "r"(a[mt][2]), "r"(a[mt][3]),
                          "r"(b[nt][0]), "r"(b[nt][1]));
                }
        }
        __syncthreads();
    }
    #undef ISSUE_TILE

    // epilogue
    #pragma unroll
    for (int mt = 0; mt < 4; mt++) {
        int row0 = rowBase + wr * 64 + mt * 16 + (lane >> 2);
        #pragma unroll
        for (int nt = 0; nt < 4; nt++) {
            int col = colBase + wc * 32 + nt * 8 + (lane & 3) * 2;
            #pragma unroll
            for (int half = 0; half < 2; half++) {
                int row = row0 + half * 8;
                float vx = acc[mt][nt][half * 2 + 0];
                float vy = acc[mt][nt][half * 2 + 1];
                if (EPI >= 1) { vx += bias[col]; vy += bias[col + 1]; }
                if (EPI == 2) { vx = tanhf(vx); vy = tanhf(vy); }
                if (EPI == 3) {
                    const float2 rr = *reinterpret_cast<const float2*>(
                        res + (size_t)row * ldc + col);
                    vx += rr.x; vy += rr.y;
                }
                if (EPI == 2 || EPI == 4) {
                    __nv_bfloat162 h2, l2;
                    split2(vx, vy, h2, l2);
                    *reinterpret_cast<unsigned*>(Chi + (size_t)row * ldc + col) =
                        *reinterpret_cast<unsigned*>(&h2);
                    *reinterpret_cast<unsigned*>(Clo + (size_t)row * ldc + col) =
                        *reinterpret_cast<unsigned*>(&l2);
                } else {
                    *reinterpret_cast<float2*>(C + (size_t)row * ldc + col) =
                        make_float2(vx, vy);
                }
            }
        }
    }
}

// ---------------- coarse top-16 -> exact fp32 rescore -> top-5 + mean ----------------
__global__ __launch_bounds__(256) void topk16_kernel(
    const float* __restrict__ src, const float* __restrict__ anchors)
{
    int n = blockIdx.x;
    int tid = threadIdx.x;
    int lane = tid & 31, w = tid >> 5;
    const float* Srow = g_S + (size_t)n * MM_;

    float v[16]; int id[16];
    #pragma unroll
    for (int i = 0; i < 16; i++) { v[i] = 3.4e38f; id[i] = 0x7fffffff; }
    for (int m = tid; m < MM_; m += 256) {
        float d = g_anorm[m] - 2.0f * Srow[m];
        if (d < v[15] || (d == v[15] && m < id[15])) {
            int p = 15;
            while (p > 0 && (d < v[p-1] || (d == v[p-1] && m < id[p-1]))) {
                v[p] = v[p-1]; id[p] = id[p-1]; p--;
            }
            v[p] = d; id[p] = m;
        }
    }

    __shared__ float sv[256];
    __shared__ int   si[256];
    __shared__ int   cand[16];
    int pos = 0;
    for (int round = 0; round < 16; round++) {
        sv[tid] = (pos < 16) ? v[pos] : 3.4e38f;
        si[tid] = (pos < 16) ? id[pos] : 0x7fffffff;
        __syncthreads();
        for (int s = 128; s > 0; s >>= 1) {
            if (tid < s) {
                float ov = sv[tid + s]; int oi = si[tid + s];
                if (ov < sv[tid] || (ov == sv[tid] && oi < si[tid])) {
                    sv[tid] = ov; si[tid] = oi;
                }
            }
            __syncthreads();
        }
        int wnr = si[0];
        if (tid == 0) cand[round] = wnr;
        if (pos < 16 && id[pos] == wnr) pos++;
        __syncthreads();
    }

    // exact fp32 rescore of 16 candidates (8 warps x 2 candidates)
    __shared__ float dex[16];
    const float* srow = src + (size_t)n * DD_;
    for (int c = w; c < 16; c += 8) {
        int m = cand[c];
        const float* a = anchors + (size_t)m * DD_;
        float s = 0.f;
        for (int i = lane; i < DD_; i += 32) s += srow[i] * a[i];
        #pragma unroll
        for (int o = 16; o; o >>= 1) s += __shfl_xor_sync(0xffffffffu, s, o);
        if (lane == 0) dex[c] = g_anorm[m] - 2.0f * s;
    }
    __syncthreads();

    __shared__ int win5[5];
    if (tid == 0) {
        bool used[16];
        #pragma unroll
        for (int i = 0; i < 16; i++) used[i] = false;
        for (int r2 = 0; r2 < 5; r2++) {
            float bv = 3.4e38f; int bi = 0x7fffffff; int bc = 0;
            for (int c = 0; c < 16; c++) {
                if (used[c]) continue;
                if (dex[c] < bv || (dex[c] == bv && cand[c] < bi)) {
                    bv = dex[c]; bi = cand[c]; bc = c;
                }
            }
            used[bc] = true; win5[r2] = bi;
        }
    }
    __syncthreads();

    // neigh mean -> split bf16
    for (int c = tid; c < DD_; c += 256) {
        float s = 0.f;
        #pragma unroll
        for (int k = 0; k < 5; k++) s += anchors[(size_t)win5[k] * DD_ + c];
        float m = s * 0.2f;
        __nv_bfloat16 h = __float2bfloat16(m);
        __nv_bfloat16 l = __float2bfloat16(m - __bfloat162float(h));
        g_neigh_hi[(size_t)n * DD_ + c] = h;
        g_neigh_lo[(size_t)n * DD_ + c] = l;
    }
}

// ---------------- BN: deterministic two-stage column stats ----------------
__global__ __launch_bounds__(256) void bn_stats_kernel(const float* __restrict__ X) {
    int b = blockIdx.x;
    int c0 = threadIdx.x, c1 = threadIdx.x + 256;
    float s0 = 0, q0 = 0, s1 = 0, q1 = 0;
    const float* p = X + (size_t)b * 128 * DD_;
    for (int r = 0; r < 128; r++) {
        float x0 = p[(size_t)r * DD_ + c0];
        float x1 = p[(size_t)r * DD_ + c1];
        s0 += x0; q0 += x0 * x0;
        s1 += x1; q1 += x1 * x1;
    }
    g_part[b * DD_ + c0] = s0;
    g_part[b * DD_ + c1] = s1;
    g_part[128 * DD_ + b * DD_ + c0] = q0;
    g_part[128 * DD_ + b * DD_ + c1] = q1;
}

__global__ void bn_finalize_kernel(const float* __restrict__ g,
                                   const float* __restrict__ bt) {
    int c = blockIdx.x * 256 + threadIdx.x;
    float s = 0, q = 0;
    for (int b = 0; b < 128; b++) {
        s += g_part[b * DD_ + c];
        q += g_part[128 * DD_ + b * DD_ + c];
    }
    float mu = s * (1.0f / NN_);
    float var = q * (1.0f / NN_) - mu * mu;
    float sc = g[c] * rsqrtf(var + 1e-5f);
    g_scale[c] = sc;
    g_shift[c] = bt[c] - mu * sc;
}

// BN apply; SPLIT: also emit hi/lo bf16 (same linear layout, ld=512)
template <bool TANH, bool SPLIT>
__global__ void bn_apply_kernel(const float* __restrict__ X, float* __restrict__ Y,
                                __nv_bfloat16* __restrict__ Yhi,
                                __nv_bfloat16* __restrict__ Ylo) {
    size_t i = ((size_t)blockIdx.x * 256 + threadIdx.x) * 4;
    int c = (int)(i & (DD_ - 1));
    float4 x  = *reinterpret_cast<const float4*>(X + i);
    float4 sc = *reinterpret_cast<const float4*>(g_scale + c);
    float4 sh = *reinterpret_cast<const float4*>(g_shift + c);
    float4 y;
    y.x = x.x * sc.x + sh.x; y.y = x.y * sc.y + sh.y;
    y.z = x.z * sc.z + sh.z; y.w = x.w * sc.w + sh.w;
    if (TANH) { y.x = tanhf(y.x); y.y = tanhf(y.y); y.z = tanhf(y.z); y.w = tanhf(y.w); }
    *reinterpret_cast<float4*>(Y + i) = y;
    if (SPLIT) {
        __nv_bfloat162 h0, l0, h1, l1;
        split2(y.x, y.y, h0, l0);
        split2(y.z, y.w, h1, l1);
        uint2 ph, pl;
        ph.x = *reinterpret_cast<unsigned*>(&h0); ph.y = *reinterpret_cast<unsigned*>(&h1);
        pl.x = *reinterpret_cast<unsigned*>(&l0); pl.y = *reinterpret_cast<unsigned*>(&l1);
        *reinterpret_cast<uint2*>(Yhi + i) = ph;
        *reinterpret_cast<uint2*>(Ylo + i) = pl;
    }
}

// ---------------- launch ----------------
static float* symAddr(const void* symbol) {
    void* p = nullptr;
    cudaGetSymbolAddress(&p, symbol);
    return (float*)p;
}

extern "C" void kernel_launch(void* const* d_in, const int* in_sizes, int n_in,
                              void* d_out, int out_size) {
    (void)in_sizes; (void)n_in; (void)out_size;
    const float* src    = (const float*)d_in[0];
    const float* anchor = (const float*)d_in[1];
    const float* W_dim  = (const float*)d_in[2];
    const float* b_dim  = (const float*)d_in[3];
    const float* W_fus  = (const float*)d_in[4];
    const float* b_fus  = (const float*)d_in[5];
    const float* W_e1   = (const float*)d_in[6];
    const float* b_e1   = (const float*)d_in[7];
    const float* W_e2   = (const float*)d_in[8];
    const float* b_e2   = (const float*)d_in[9];
    const float* g1     = (const float*)d_in[10];
    const float* bt1    = (const float*)d_in[11];
    const float* g2     = (const float*)d_in[12];
    const float* bt2    = (const float*)d_in[13];
    const float* W_d    = (const float*)d_in[14];
    const float* b_d    = (const float*)d_in[15];
    const float* g_d    = (const float*)d_in[16];
    const float* bt_d   = (const float*)d_in[17];
    float* out = (float*)d_out;

    float* pS      = symAddr(g_S);
    float* pComb   = symAddr(g_comb);
    float* pCombn  = symAddr(g_combn);
    float* pR      = symAddr(g_r);
    float* pDec    = symAddr(g_dec);
    __nv_bfloat16* pSrcBf   = (__nv_bfloat16*)symAddr(g_src_bf);
    __nv_bfloat16* pAnchBf  = (__nv_bfloat16*)symAddr(g_anch_bf);
    __nv_bfloat16* pNeighH  = (__nv_bfloat16*)symAddr(g_neigh_hi);
    __nv_bfloat16* pNeighL  = (__nv_bfloat16*)symAddr(g_neigh_lo);
    __nv_bfloat16* pCatH    = (__nv_bfloat16*)symAddr(g_cat_hi);
    __nv_bfloat16* pCatL    = (__nv_bfloat16*)symAddr(g_cat_lo);
    __nv_bfloat16* pCombnH  = (__nv_bfloat16*)symAddr(g_combn_hi);
    __nv_bfloat16* pCombnL  = (__nv_bfloat16*)symAddr(g_combn_lo);
    __nv_bfloat16* pHH      = (__nv_bfloat16*)symAddr(g_h_hi);
    __nv_bfloat16* pHL      = (__nv_bfloat16*)symAddr(g_h_lo);
    __nv_bfloat16* pC2H     = (__nv_bfloat16*)symAddr(g_c2_hi);
    __nv_bfloat16* pC2L     = (__nv_bfloat16*)symAddr(g_c2_lo);
    __nv_bfloat16* pWdimH   = (__nv_bfloat16*)symAddr(g_WdimT_hi);
    __nv_bfloat16* pWdimL   = (__nv_bfloat16*)symAddr(g_WdimT_lo);
    __nv_bfloat16* pWfusH   = (__nv_bfloat16*)symAddr(g_WfusT_hi);
    __nv_bfloat16* pWfusL   = (__nv_bfloat16*)symAddr(g_WfusT_lo);
    __nv_bfloat16* pWe1H    = (__nv_bfloat16*)symAddr(g_We1T_hi);
    __nv_bfloat16* pWe1L    = (__nv_bfloat16*)symAddr(g_We1T_lo);
    __nv_bfloat16* pWe2H    = (__nv_bfloat16*)symAddr(g_We2T_hi);
    __nv_bfloat16* pWe2L    = (__nv_bfloat16*)symAddr(g_We2T_lo);
    __nv_bfloat16* pWdH     = (__nv_bfloat16*)symAddr(g_WdT_hi);
    __nv_bfloat16* pWdL     = (__nv_bfloat16*)symAddr(g_WdT_lo);

    const int T = 256;

    // 0) bf16 copies for the coarse distance GEMM + weight transpose/split
    tobf16_kernel<<<(NN_ * DD_ / 4) / T, T>>>(src, pSrcBf);
    tobf16_kernel<<<(MM_ * DD_ / 4) / T, T>>>(anchor, pAnchBf);
    tsplit_kernel<<<dim3(DD_ / 32, DD_ / 32), dim3(32, 8)>>>(W_dim, pWdimH, pWdimL, DD_, DD_);
    tsplit_kernel<<<dim3(DD_ / 32, 2 * DD_ / 32), dim3(32, 8)>>>(W_fus, pWfusH, pWfusL, 2 * DD_, DD_);
    tsplit_kernel<<<dim3(FF_ / 32, DD_ / 32), dim3(32, 8)>>>(W_e1, pWe1H, pWe1L, DD_, FF_);
    tsplit_kernel<<<dim3(DD_ / 32, FF_ / 32), dim3(32, 8)>>>(W_e2, pWe2H, pWe2L, FF_, DD_);
    tsplit_kernel<<<dim3(DD_ / 32, DD_ / 32), dim3(32, 8)>>>(W_d, pWdH, pWdL, DD_, DD_);

    // 1) anchor norms (fp32)
    anorm_kernel<<<MM_ / 8, T>>>(anchor);

    // 2) coarse S = src_bf @ anchor_bf^T (single-pass bf16)
    gemm_bf16_mp<1, 0><<<dim3(MM_ / 128, NN_ / 128), T>>>(
        pSrcBf, nullptr, pAnchBf, nullptr, nullptr, nullptr,
        pS, nullptr, nullptr, DD_, DD_, DD_, MM_);

    // 3) top-16 -> exact rescore -> top-5 -> neigh (split bf16)
    topk16_kernel<<<NN_, T>>>(src, anchor);

    // 4) cat left = split(src); cat right = neigh @ W_dim + b_dim (split epilogue)
    pack_split_kernel<<<(NN_ * DD_ / 4) / T, T>>>(src);
    gemm_bf16_mp<3, 4><<<dim3(DD_ / 128, NN_ / 128), T>>>(
        pNeighH, pNeighL, pWdimH, pWdimL, b_dim, nullptr,
        nullptr, pCatH + DD_, pCatL + DD_, DD_, DD_, DD_, 2 * DD_);

    // 5) comb = cat @ W_fus + b_fus (K=1024) -> fp32
    gemm_bf16_mp<3, 1><<<dim3(DD_ / 128, NN_ / 128), T>>>(
        pCatH, pCatL, pWfusH, pWfusL, b_fus, nullptr,
        pComb, nullptr, nullptr, 2 * DD_, 2 * DD_, 2 * DD_, DD_);

    // 6) BN1 -> combn fp32 + split bf16
    bn_stats_kernel<<<128, T>>>(pComb);
    bn_finalize_kernel<<<2, T>>>(g1, bt1);
    bn_apply_kernel<false, true><<<(NN_ * DD_ / 4) / T, T>>>(pComb, pCombn, pCombnH, pCombnL);

    // 7) h = tanh(combn @ W_e1 + b_e1) -> split bf16 directly (no fp32 h)
    gemm_bf16_mp<3, 2><<<dim3(FF_ / 128, NN_ / 128), T>>>(
        pCombnH, pCombnL, pWe1H, pWe1L, b_e1, nullptr,
        nullptr, pHH, pHL, DD_, DD_, DD_, FF_);

    // 8) r = combn + (h @ W_e2 + b_e2) (K=2048) -> fp32
    gemm_bf16_mp<3, 3><<<dim3(DD_ / 128, NN_ / 128), T>>>(
        pHH, pHL, pWe2H, pWe2L, b_e2, pCombn,
        pR, nullptr, nullptr, FF_, FF_, FF_, DD_);

    // 9) BN2 -> comb2 split bf16
    bn_stats_kernel<<<128, T>>>(pR);
    bn_finalize_kernel<<<2, T>>>(g2, bt2);
    bn_apply_kernel<false, true><<<(NN_ * DD_ / 4) / T, T>>>(pR, pComb, pC2H, pC2L);

    // 10) dec = comb2 @ W_d + b_d -> fp32
    gemm_bf16_mp<3, 1><<<dim3(DD_ / 128, NN_ / 128), T>>>(
        pC2H, pC2L, pWdH, pWdL, b_d, nullptr,
        pDec, nullptr, nullptr, DD_, DD_, DD_, DD_);

    // 11) out = tanh(BN(dec))
    bn_stats_kernel<<<128, T>>>(pDec);
    bn_finalize_kernel<<<2, T>>>(g_d, bt_d);
    bn_apply_kernel<true, false><<<(NN_ * DD_ / 4) / T, T>>>(pDec, out, nullptr, nullptr);
}